// round 2
// baseline (speedup 1.0000x reference)
#include <cuda_runtime.h>
#include <cstdint>
#include <cstddef>

#define Nn 4096
#define Ll 128
#define Kk 16
#define LEFTn 3968
#define LEVEL_BLOCKS 148

// ---------------- scratch (device globals; no allocation allowed) ----------------
__device__ float g_A[(size_t)Nn * Nn];        // working copy of A -> becomes A_L
__device__ float g_R[(size_t)Nn * Nn];        // right (starts identity)
__device__ float g_Gpart[4 * 128 * Nn];       // K-split partials of G = B @ R
__device__ float g_G[128 * Nn];               // G summed
__device__ float g_P[128 * Nn];               // P = G - M_eff @ F
__device__ float g_F[128 * Nn];               // F = R[inact,:]
__device__ unsigned char g_act[Nn];           // active flags
__device__ unsigned int g_bar[Ll];            // per-level barrier counters

// ---------------- init: copy A, R=I, flags, barrier reset ----------------
__global__ void k_init(const float* __restrict__ A, const int* __restrict__ inact) {
    size_t tid = (size_t)blockIdx.x * blockDim.x + threadIdx.x;
    size_t stride = (size_t)gridDim.x * blockDim.x;
    const float4* A4 = (const float4*)A;
    float4* gA4 = (float4*)g_A;
    float4* gR4 = (float4*)g_R;
    size_t n4 = (size_t)Nn * Nn / 4;
    for (size_t i = tid; i < n4; i += stride) {
        gA4[i] = A4[i];
        size_t e = i * 4;
        int r = (int)(e >> 12);
        int c = (int)(e & 4095);
        float4 v = make_float4(0.f, 0.f, 0.f, 0.f);
        int d = r - c;
        if (d >= 0 && d < 4) ((float*)&v)[d] = 1.0f;
        gR4[i] = v;
    }
    if (tid < Ll) g_bar[tid] = 0u;
    if (tid < Nn) {
        unsigned char f = 1;
        for (int j = 0; j < Ll; ++j)
            if (__ldg(&inact[j]) == (int)tid) f = 0;
        g_act[tid] = f;
    }
}

// ---------------- persistent level loop with software grid barrier ----------------
__global__ void __launch_bounds__(256) k_levels(const float* __restrict__ Os,
                                                const int* __restrict__ sel_idx,
                                                const int* __restrict__ drop_idx,
                                                float* __restrict__ out_wav) {
    __shared__ int s_sel[Kk];
    __shared__ float s_O[Kk * Kk];
    __shared__ float s_Ass[Kk][Kk];
    __shared__ float s_T[Kk][Kk];
    const int tid = threadIdx.x;
    const int t = blockIdx.x * 256 + tid;
    const unsigned int nb = gridDim.x;

    for (int l = 0; l < Ll; ++l) {
        __syncthreads();
        if (tid < Kk) s_sel[tid] = __ldg(&sel_idx[l * Kk + tid]);
        s_O[tid] = __ldg(&Os[l * Kk * Kk + tid]);
        __syncthreads();
        const int drp = __ldg(&drop_idx[l]);

        if (t < 16384) {
            // A row-rotation for columns not in sel; 4 threads per column (4 rows each)
            const int c = t >> 2;
            const int q = t & 3;
            bool insel = false;
            #pragma unroll
            for (int k = 0; k < Kk; ++k) insel |= (c == s_sel[k]);
            float a[Kk];
            if (!insel) {
                #pragma unroll
                for (int k = 0; k < Kk; ++k)
                    a[k] = __ldcg(&g_A[(size_t)s_sel[k] * Nn + c]);
            }
            __syncwarp();
            if (!insel) {
                float v[4];
                #pragma unroll
                for (int jj = 0; jj < 4; ++jj) {
                    const int j = q * 4 + jj;
                    float s = 0.f;
                    #pragma unroll
                    for (int k = 0; k < Kk; ++k) s += s_O[j * Kk + k] * a[k];
                    v[jj] = s;
                }
                #pragma unroll
                for (int jj = 0; jj < 4; ++jj) {
                    const int r = s_sel[q * 4 + jj];
                    __stcg(&g_A[(size_t)r * Nn + c], v[jj]);   // row write
                    __stcg(&g_A[(size_t)c * Nn + r], v[jj]);   // symmetric col write
                    if (r == drp) out_wav[(size_t)l * Nn + c] = v[jj];
                }
            }
        } else if (t < 32768) {
            // right row-rotation, all columns
            const int c = (t - 16384) >> 2;
            const int q = t & 3;
            float a[Kk];
            #pragma unroll
            for (int k = 0; k < Kk; ++k)
                a[k] = __ldcg(&g_R[(size_t)s_sel[k] * Nn + c]);
            __syncwarp();
            #pragma unroll
            for (int jj = 0; jj < 4; ++jj) {
                const int j = q * 4 + jj;
                float s = 0.f;
                #pragma unroll
                for (int k = 0; k < Kk; ++k) s += s_O[j * Kk + k] * a[k];
                __stcg(&g_R[(size_t)s_sel[j] * Nn + c], s);
            }
        }

        // sel x sel block: O * Ass * O^T by the last block
        if (blockIdx.x == nb - 1) {
            const int i = tid >> 4, j = tid & 15;
            s_Ass[i][j] = __ldcg(&g_A[(size_t)s_sel[i] * Nn + s_sel[j]]);
            __syncthreads();
            float ts = 0.f;
            #pragma unroll
            for (int k = 0; k < Kk; ++k) ts += s_O[i * Kk + k] * s_Ass[k][j];
            s_T[i][j] = ts;
            __syncthreads();
            float b2 = 0.f;
            #pragma unroll
            for (int k = 0; k < Kk; ++k) b2 += s_T[i][k] * s_O[j * Kk + k];
            __stcg(&g_A[(size_t)s_sel[i] * Nn + s_sel[j]], b2);
            if (s_sel[i] == drp) out_wav[(size_t)l * Nn + s_sel[j]] = b2;
        }

        // grid barrier (canonical CG-style)
        __syncthreads();
        if (tid == 0) {
            __threadfence();
            atomicAdd(&g_bar[l], 1u);
            while (((volatile unsigned int*)g_bar)[l] < nb) { __nanosleep(32); }
        }
        __syncthreads();
    }
}

// ---------------- G = A_L[inact,:] @ R   (K-split x4 into g_Gpart) ----------------
__global__ void __launch_bounds__(256) k_gemmG(const int* __restrict__ inact) {
    __shared__ float sB[128][33];
    __shared__ float sR[32][65];
    __shared__ int s_in[128];
    const int tid = threadIdx.x;
    if (tid < 128) s_in[tid] = __ldg(&inact[tid]);
    __syncthreads();
    const int c0 = blockIdx.x * 64;  // 64 col tiles
    const int ks = blockIdx.y;       // 4 K-splits
    const int rg = tid >> 4;         // 16 row groups of 8
    const int cg = tid & 15;         // 16 col groups of 4
    float acc[8][4] = {};
    for (int k0 = ks * 1024; k0 < ks * 1024 + 1024; k0 += 32) {
        __syncthreads();
        for (int x = tid; x < 128 * 32; x += 256) {
            const int i = x >> 5, kk = x & 31;
            sB[i][kk] = __ldg(&g_A[(size_t)s_in[i] * Nn + k0 + kk]);
        }
        for (int x = tid; x < 32 * 64; x += 256) {
            const int kk = x >> 6, c = x & 63;
            sR[kk][c] = __ldg(&g_R[(size_t)(k0 + kk) * Nn + c0 + c]);
        }
        __syncthreads();
        #pragma unroll 4
        for (int kk = 0; kk < 32; ++kk) {
            float b[4];
            #pragma unroll
            for (int y = 0; y < 4; ++y) b[y] = sR[kk][cg * 4 + y];
            #pragma unroll
            for (int x = 0; x < 8; ++x) {
                const float av = sB[rg * 8 + x][kk];
                #pragma unroll
                for (int y = 0; y < 4; ++y) acc[x][y] += av * b[y];
            }
        }
    }
    #pragma unroll
    for (int x = 0; x < 8; ++x)
        #pragma unroll
        for (int y = 0; y < 4; ++y)
            g_Gpart[((size_t)ks * 128 + rg * 8 + x) * Nn + c0 + cg * 4 + y] = acc[x][y];
}

// ---------------- F, G-sum, P = G - M_eff @ F ----------------
__global__ void __launch_bounds__(256) k_P(const int* __restrict__ inact) {
    __shared__ float sF[128][33];
    __shared__ int s_in[128];
    const int tid = threadIdx.x;
    if (tid < 128) s_in[tid] = __ldg(&inact[tid]);
    __syncthreads();
    const int c0 = blockIdx.x * 32;
    for (int x = tid; x < 128 * 32; x += 256) {
        const int j = x >> 5, c = x & 31;
        const float f = __ldg(&g_R[(size_t)s_in[j] * Nn + c0 + c]);
        sF[j][c] = f;
        g_F[(size_t)j * Nn + c0 + c] = f;
    }
    __syncthreads();
    const int col = tid & 31;
    const int i0 = (tid >> 5) * 16;
    float acc[16];
    #pragma unroll
    for (int ii = 0; ii < 16; ++ii) {
        float s = 0.f;
        #pragma unroll
        for (int sp = 0; sp < 4; ++sp)
            s += g_Gpart[((size_t)sp * 128 + i0 + ii) * Nn + c0 + col];
        g_G[(size_t)(i0 + ii) * Nn + c0 + col] = s;
        acc[ii] = s;
    }
    for (int j = 0; j < 128; ++j) {
        const float f = sF[j][col];
        #pragma unroll
        for (int ii = 0; ii < 16; ++ii) {
            float m = __ldg(&g_A[(size_t)s_in[i0 + ii] * Nn + s_in[j]]);
            if (i0 + ii == j) m *= 2.0f;
            acc[ii] -= m * f;
        }
    }
    #pragma unroll
    for (int ii = 0; ii < 16; ++ii)
        g_P[(size_t)(i0 + ii) * Nn + c0 + col] = acc[ii];
}

// ---------------- A_rec = A - F^T P - G^T F  (rank-256 update) ----------------
__global__ void __launch_bounds__(256) k_Arec(const float* __restrict__ A,
                                              float* __restrict__ out) {
    __shared__ float sU[16][132];
    __shared__ float sV[16][132];
    const int tid = threadIdx.x;
    const int r0 = blockIdx.y * 128, c0 = blockIdx.x * 128;
    const int tr = tid >> 4, tc = tid & 15;
    float acc[8][8] = {};
    for (int k0 = 0; k0 < 256; k0 += 16) {
        __syncthreads();
        for (int x = tid; x < 2048; x += 256) {
            const int kk = x >> 7, rr = x & 127;
            const int k = k0 + kk;
            if (k < 128) {
                sU[kk][rr] = g_F[(size_t)k * Nn + r0 + rr];
                sV[kk][rr] = g_P[(size_t)k * Nn + c0 + rr];
            } else {
                sU[kk][rr] = g_G[(size_t)(k - 128) * Nn + r0 + rr];
                sV[kk][rr] = g_F[(size_t)(k - 128) * Nn + c0 + rr];
            }
        }
        __syncthreads();
        #pragma unroll
        for (int kk = 0; kk < 16; ++kk) {
            float a[8], b[8];
            #pragma unroll
            for (int x = 0; x < 8; ++x) a[x] = sU[kk][tr * 8 + x];
            #pragma unroll
            for (int y = 0; y < 8; ++y) b[y] = sV[kk][tc * 8 + y];
            #pragma unroll
            for (int x = 0; x < 8; ++x)
                #pragma unroll
                for (int y = 0; y < 8; ++y) acc[x][y] += a[x] * b[y];
        }
    }
    #pragma unroll
    for (int x = 0; x < 8; ++x) {
        const size_t r = (size_t)(r0 + tr * 8 + x);
        const size_t base = r * Nn + c0 + tc * 8;
        float4 a0 = __ldg((const float4*)(A + base));
        float4 a1 = __ldg((const float4*)(A + base + 4));
        float4 o0, o1;
        o0.x = a0.x - acc[x][0]; o0.y = a0.y - acc[x][1];
        o0.z = a0.z - acc[x][2]; o0.w = a0.w - acc[x][3];
        o1.x = a1.x - acc[x][4]; o1.y = a1.y - acc[x][5];
        o1.z = a1.z - acc[x][6]; o1.w = a1.w - acc[x][7];
        *(float4*)(out + base) = o0;
        *(float4*)(out + base + 4) = o1;
    }
}

// ---------------- epilogue: D, core_wavelets, mother, father ----------------
__global__ void k_epi(const int* __restrict__ active_idx,
                      const int* __restrict__ inact,
                      float* __restrict__ out) {
    const size_t D4 = (size_t)Nn * Nn / 4;            // 4194304
    const size_t C4 = (size_t)LEFTn * Nn / 4;         // 4063232
    const size_t M4 = (size_t)Ll * Nn / 4;            // 131072
    const size_t total = D4 + C4 + M4 + C4;
    const size_t oD = 16777216ull / 4;                // region offsets (float4 units)
    const size_t oC = 34078720ull / 4;
    const size_t oM = 50331648ull / 4;
    const size_t oF = 50855936ull / 4;
    float4* o = (float4*)out;
    const float4* gA4 = (const float4*)g_A;
    const float4* gR4 = (const float4*)g_R;
    size_t tid = (size_t)blockIdx.x * blockDim.x + threadIdx.x;
    size_t stride = (size_t)gridDim.x * blockDim.x;
    for (size_t i = tid; i < total; i += stride) {
        if (i < D4) {
            const size_t e = i * 4;
            const int r = (int)(e >> 12);
            const int c = (int)(e & 4095);
            float4 v = gA4[i];
            const unsigned char ar = g_act[r];
            float* vf = (float*)&v;
            #pragma unroll
            for (int u = 0; u < 4; ++u) {
                const int cc = c + u;
                const bool keep = (r == cc) || (ar && g_act[cc]);
                if (!keep) vf[u] = 0.f;
            }
            o[oD + i] = v;
        } else if (i < D4 + C4) {
            const size_t x = i - D4;
            const int row = (int)(x >> 10);
            const int c4 = (int)(x & 1023);
            const int src = __ldg(&active_idx[row]);
            o[oC + x] = gA4[(size_t)src * 1024 + c4];
        } else if (i < D4 + C4 + M4) {
            const size_t x = i - D4 - C4;
            const int row = (int)(x >> 10);
            const int c4 = (int)(x & 1023);
            const int src = __ldg(&inact[row]);
            o[oM + x] = gR4[(size_t)src * 1024 + c4];
        } else {
            const size_t x = i - D4 - C4 - M4;
            const int row = (int)(x >> 10);
            const int c4 = (int)(x & 1023);
            const int src = __ldg(&active_idx[row]);
            o[oF + x] = gR4[(size_t)src * 1024 + c4];
        }
    }
}

// ---------------- launch ----------------
extern "C" void kernel_launch(void* const* d_in, const int* in_sizes, int n_in,
                              void* d_out, int out_size) {
    const float* A = (const float*)d_in[0];
    const float* Os = (const float*)d_in[1];
    const int* sel = (const int*)d_in[2];
    const int* drp = (const int*)d_in[3];
    const int* act = (const int*)d_in[4];
    const int* inact = (const int*)d_in[5];
    float* out = (float*)d_out;

    k_init<<<2048, 256>>>(A, inact);
    k_levels<<<LEVEL_BLOCKS, 256>>>(Os, sel, drp, out + 2ull * Nn * Nn);
    dim3 gG(64, 4);
    k_gemmG<<<gG, 256>>>(inact);
    k_P<<<128, 256>>>(inact);
    dim3 gA(32, 32);
    k_Arec<<<gA, 256>>>(A, out);
    k_epi<<<1024, 256>>>(act, inact, out);
}